// round 16
// baseline (speedup 1.0000x reference)
#include <cuda_runtime.h>
#include <math.h>
#include <stdint.h>

#define B_N        262144
#define CHUNK      2048                    // per main block (16 warps x 128)
#define HALO       32
#define NMAIN      (B_N / CHUNK)           // 128 main blocks
#define NRED       20                      // reducer blocks (bid 0..19)
#define NBLK       (NMAIN + NRED)          // 148 = exactly 1 block/SM
#define TPB        512
#define SPIN_LEN   365
#define TRAIN_LEN  200000
#define N_OBS      (TRAIN_LEN - SPIN_LEN)  // 199635
#define Y_ALIGN    368                     // first 16B-aligned idx in y slice
#define N_Y4       ((TRAIN_LEN - Y_ALIGN) / 4)   // 49908 float4s
#define YB         5                       // 20*512*5 = 51200 >= 49908
#define OB4        (B_N / 4)               // 65536 float4s in obss
#define ML_C       2.9086f
#define SL_C       1.898f
#define LOG2E      1.4426950408889634f

// dynamic smem: 10 arrays x 2048 f + hnout 4096 f = 96 KB used.
// Request 120 KB so two blocks can never co-reside on one SM.
#define SMEM_ALLOC (120 * 1024)

__device__ float    g_partS[NRED];
__device__ float    g_partS2[NRED];
__device__ float    g_obsstd;
__device__ unsigned g_count = 0;
__device__ unsigned g_flag  = 0;

__global__ void __launch_bounds__(TPB)
k_all(const float2* __restrict__ x, const float* __restrict__ y,
      const float* __restrict__ w_yom, const float* __restrict__ w_gw,
      const float* __restrict__ w_lm,  const float* __restrict__ w_fm,
      const float* __restrict__ b0p,   const float* __restrict__ wb2p,
      float* __restrict__ out) {
    extern __shared__ float smem[];
    const int tid = threadIdx.x;
    const int bid = blockIdx.x;

    float* __restrict__ hnout = out + 10 * B_N;     // (B,2) interleaved
    float* __restrict__ obss  = out + 12 * B_N;

    // =====================================================================
    // REDUCER BLOCKS (bid 0..NRED-1): obsstd + release + obss stores.
    // =====================================================================
    if (bid < NRED) {
        const int r = bid;
        __shared__ int   sh_last;
        __shared__ float sh_std;

        unsigned gen = 0;
        if (tid == 0) gen = *(volatile unsigned*)&g_flag;

        // front-batched predicated loads (MLP=5, one DRAM latency)
        float4 v[YB];
        const int t0 = r * TPB + tid;               // 0..10239
#pragma unroll
        for (int k = 0; k < YB; ++k) {
            int yi = t0 + k * (NRED * TPB);
            v[k] = (yi < N_Y4)
                 ? *reinterpret_cast<const float4*>(y + Y_ALIGN + 4 * yi)
                 : make_float4(0.f, 0.f, 0.f, 0.f);
        }
        float s = 0.f, s2 = 0.f;
#pragma unroll
        for (int k = 0; k < YB; ++k) {
            s  += v[k].x + v[k].y + v[k].z + v[k].w;
            s2 += v[k].x*v[k].x + v[k].y*v[k].y
                + v[k].z*v[k].z + v[k].w*v[k].w;
        }
        if (r == 0 && tid < 3) {                    // elems 365..367
            float t = y[SPIN_LEN + tid];
            s += t; s2 += t * t;
        }
#pragma unroll
        for (int o = 16; o; o >>= 1) {
            s  += __shfl_down_sync(0xffffffffu, s, o);
            s2 += __shfl_down_sync(0xffffffffu, s2, o);
        }
        __shared__ float rs[16], rs2[16];
        int w = tid >> 5, l = tid & 31;
        if (l == 0) { rs[w] = s; rs2[w] = s2; }
        __syncthreads();
        if (tid == 0) {
            float a = 0.f, b = 0.f;
#pragma unroll
            for (int i = 0; i < TPB / 32; i++) { a += rs[i]; b += rs2[i]; }
            g_partS[r]  = a;
            g_partS2[r] = b;
            __threadfence();
            unsigned old = atomicAdd(&g_count, 1);
            sh_last = (old == NRED - 1);
        }
        __syncthreads();

        if (sh_last && tid < 32) {                  // finalize in warp 0
            double ds = 0.0, ds2 = 0.0;
            if (tid < NRED) {
                ds  = (double)__ldcg(&g_partS[tid]);
                ds2 = (double)__ldcg(&g_partS2[tid]);
            }
#pragma unroll
            for (int o = 16; o; o >>= 1) {
                ds  += __shfl_down_sync(0xffffffffu, ds, o);
                ds2 += __shfl_down_sync(0xffffffffu, ds2, o);
            }
            if (tid == 0) {
                double n = (double)N_OBS;
                g_obsstd = (float)sqrt((ds2 - ds * ds / n) / (n - 1.0));
                g_count  = 0;                       // reset for next replay
                __threadfence();
                atomicAdd(&g_flag, 1);              // release
            }
        }

        if (tid == 0) {
            while (*(volatile unsigned*)&g_flag == gen) __nanosleep(32);
            __threadfence();
            sh_std = *(volatile float*)&g_obsstd;
        }
        __syncthreads();
        const float obsstd = sh_std;
        const float4 st4 = make_float4(obsstd, obsstd, obsstd, obsstd);

        // obss: 65536 float4 over 10240 threads, predicated
#pragma unroll
        for (int it = 0; it < 7; ++it) {
            int idx4 = it * (NRED * TPB) + r * TPB + tid;
            if (idx4 < OB4)
                *reinterpret_cast<float4*>(&obss[4 * idx4]) = st4;
        }
        return;
    }

    // =====================================================================
    // MAIN BLOCKS: affine scan -> stage outputs in SMEM -> TMA bulk stores.
    // Replaces 12 STG.128/thread (12-cyc issue each) with STS + cp.async.bulk.
    // =====================================================================
    const int mb    = bid - NRED;                   // 0..NMAIN-1
    const int lane  = tid & 31;
    const int wid   = tid >> 5;
    const int wbase = mb * CHUNK + wid * 128;       // warp's first element

    const unsigned gen = *(volatile unsigned*)&g_flag;   // replay-safe

    // ---- front-batched loads: 4 owned elems (2x LDG.128) + 1 halo elem
    const int og  = wbase + 4 * lane;               // global element index
    const int ogl = (og - mb * CHUNK);              // local [0, CHUNK)
    float4 xlo = *reinterpret_cast<const float4*>(x + og);      // elems 0,1
    float4 xhi = *reinterpret_cast<const float4*>(x + og + 2);  // elems 2,3
    const int hg = wbase - HALO + lane;
    float2 hx = make_float2(0.f, 0.f);
    if (hg >= 0) hx = x[hg];                        // only mb0/warp0 skips

    // ---- scalar gates (uniform, fast-math) ----
    const float e1 = __expf(w_yom[0]);
    const float e2 = __expf(w_gw[0]);
    const float e3 = __expf(w_lm[0]);
    const float e4 = __expf(w_fm[0]);
    const float inv_denom = __fdividef(1.0f, e1 + e2 + e3 + e4);
    const float oo    = e1 * inv_denom;
    const float oogw  = e2 * inv_denom;
    const float ol1   = e3 * inv_denom;
    const float fbase = 1.0f - oo - oogw;
    const float ws2 = wb2p[0] * (LOG2E / SL_C);     // exp2-domain slope
    const float zc2 = (b0p[0] - ML_C * wb2p[0] / SL_C) * LOG2E;

    // ---- sigmoids (MUFU.EX2 path) ----
    const float u0 = xlo.x, u1 = xlo.z, u2 = xhi.x, u3 = xhi.z;
    const float ol0 = __fdividef(ol1, 1.0f + exp2f(-fmaf(xlo.y, ws2, zc2)));
    const float ol1v= __fdividef(ol1, 1.0f + exp2f(-fmaf(xlo.w, ws2, zc2)));
    const float ol2 = __fdividef(ol1, 1.0f + exp2f(-fmaf(xhi.y, ws2, zc2)));
    const float ol3 = __fdividef(ol1, 1.0f + exp2f(-fmaf(xhi.w, ws2, zc2)));
    const float f0 = fbase - ol0, f1 = fbase - ol1v;
    const float f2 = fbase - ol2, f3 = fbase - ol3;

    float fh = 0.f, uh = 0.f;
    if (hg >= 0) {
        float olh = __fdividef(ol1, 1.0f + exp2f(-fmaf(hx.y, ws2, zc2)));
        fh = fbase - olh;
        uh = hx.x;
    }

    // ---- halo: ordered butterfly reduction of affine (F,U); c_base = U(0)
    float c_base;
    {
        float F = fh, U = uh;
#pragma unroll
        for (int s = 1; s < 32; s <<= 1) {
            float Fo = __shfl_xor_sync(0xffffffffu, F, s);
            float Uo = __shfl_xor_sync(0xffffffffu, U, s);
            bool lower = (lane & s) == 0;
            float Fhi = lower ? Fo : F;
            float Uhi = lower ? Uo : U;
            float Flo = lower ? F  : Fo;
            float Ulo = lower ? U  : Uo;
            U = fmaf(Fhi, Ulo, Uhi);                // hi ∘ lo
            F = Fhi * Flo;
        }
        c_base = U;
    }

    // ---- owned: compose 4 elems (tree), inclusive shuffle scan, excl shift
    float Fp, Up;
    {
        float F01 = f1 * f0,  U01 = fmaf(f1, u0, u1);
        float F23 = f3 * f2,  U23 = fmaf(f3, u2, u3);
        float F = F23 * F01;
        float U = fmaf(F23, U01, U23);
#pragma unroll
        for (int d = 1; d < 32; d <<= 1) {
            float Fi = __shfl_up_sync(0xffffffffu, F, d);
            float Ui = __shfl_up_sync(0xffffffffu, U, d);
            if (lane >= d) {
                U = fmaf(F, Ui, U);
                F = F * Fi;
            }
        }
        Fp = __shfl_up_sync(0xffffffffu, F, 1);     // exclusive
        Up = __shfl_up_sync(0xffffffffu, U, 1);
        if (lane == 0) { Fp = 1.f; Up = 0.f; }
    }
    const float c0 = fmaf(Fp, c_base, Up);          // state before elem 0
    const float c1 = fmaf(f0, c0, u0);
    const float c2 = fmaf(f1, c1, u1);
    const float c3 = fmaf(f2, c2, u2);

    const float h0 = oo * c0, h1 = oo * c1, h2 = oo * c2, h3 = oo * c3;

    // ---- stage all outputs in shared (STS.128, ~4x cheaper issue) ----
    // layout: array k (k=0..9) at floats [k*2048, k*2048+2048); hnout at 20480
#define SSTORE(k, val) \
    *reinterpret_cast<float4*>(&smem[(k) * CHUNK + ogl]) = (val)

    SSTORE(0, make_float4(h0, h1, h2, h3));                       // h_n
    SSTORE(1, make_float4(c0, c1, c2, c3));                       // c_n
    SSTORE(2, make_float4(ol0*c0, ol1v*c1, ol2*c2, ol3*c3));      // l_n
    SSTORE(3, make_float4(oogw*c0, oogw*c1, oogw*c2, oogw*c3));   // gw_n
    SSTORE(4, make_float4(0.f, 0.f, 0.f, 0.f));                   // bp_n
    SSTORE(5, make_float4(0.f, 0.f, 0.f, 0.f));                   // gate_ib
    SSTORE(6, make_float4(oo, oo, oo, oo));                       // gate_oo
    SSTORE(7, make_float4(oogw, oogw, oogw, oogw));               // gate_oogw
    SSTORE(8, make_float4(ol0, ol1v, ol2, ol3));                  // gate_ol
    SSTORE(9, make_float4(f0, f1, f2, f3));                       // gate_f
#undef SSTORE

    // ---- per-warp poll for obsstd (reducers released long ago) ----
    while (*(volatile unsigned*)&g_flag == gen) __nanosleep(64);
    __threadfence();
    const float obsstd = *(volatile float*)&g_obsstd;

    // hnout staged interleaved {h, std}
    *reinterpret_cast<float4*>(&smem[10 * CHUNK + 2 * ogl]) =
        make_float4(h0, obsstd, h1, obsstd);
    *reinterpret_cast<float4*>(&smem[10 * CHUNK + 2 * ogl + 4]) =
        make_float4(h2, obsstd, h3, obsstd);

    __syncthreads();

    // ---- TMA bulk stores: 11 copies issued by threads 0..10 ----
    if (tid < 11) {
        asm volatile("fence.proxy.async;" ::: "memory");
        const unsigned soff = (tid < 10) ? (unsigned)(tid * CHUNK)
                                         : (unsigned)(10 * CHUNK);
        const unsigned szb  = (tid < 10) ? (CHUNK * 4u) : (2u * CHUNK * 4u);
        float* dst = (tid < 10)
                   ? (out + (size_t)tid * B_N + (size_t)mb * CHUNK)
                   : (hnout + 2 * (size_t)mb * CHUNK);
        unsigned saddr = (unsigned)__cvta_generic_to_shared(smem + soff);
        asm volatile(
            "cp.async.bulk.global.shared::cta.bulk_group [%0], [%1], %2;"
            :: "l"(dst), "r"(saddr), "r"(szb) : "memory");
        asm volatile("cp.async.bulk.commit_group;" ::: "memory");
        asm volatile("cp.async.bulk.wait_group 0;" ::: "memory");
    }
}

// ---------------------------------------------------------------------------
extern "C" void kernel_launch(void* const* d_in, const int* in_sizes, int n_in,
                              void* d_out, int out_size) {
    const float* x = (const float*)d_in[0];
    const float* y = (const float*)d_in[1];

    int base = (n_in >= 10) ? 4 : 2;
    const float* w_yom = (const float*)d_in[base + 0];
    const float* w_gw  = (const float*)d_in[base + 1];
    const float* w_lm  = (const float*)d_in[base + 2];
    const float* w_fm  = (const float*)d_in[base + 3];
    const float* b0p   = (const float*)d_in[base + 4];
    const float* wb2p  = (const float*)d_in[base + 5];

    cudaFuncSetAttribute(k_all, cudaFuncAttributeMaxDynamicSharedMemorySize,
                         SMEM_ALLOC);
    k_all<<<NBLK, TPB, SMEM_ALLOC>>>((const float2*)x, y,
                                     w_yom, w_gw, w_lm, w_fm, b0p, wb2p,
                                     (float*)d_out);
}

// round 17
// speedup vs baseline: 1.1522x; 1.1522x over previous
#include <cuda_runtime.h>
#include <math.h>
#include <stdint.h>

#define B_N        262144
#define CHUNK      2048                    // per main block (8 warps x 256)
#define HALO       32
#define NMAIN      (B_N / CHUNK)           // 128 main blocks
#define NRED       20                      // reducer blocks (bid 0..19)
#define NBLK       (NMAIN + NRED)          // 148 = exactly 1 block/SM
#define TPB        256
#define SEG        8
#define SPIN_LEN   365
#define TRAIN_LEN  200000
#define N_OBS      (TRAIN_LEN - SPIN_LEN)  // 199635
#define Y_ALIGN    368                     // first 16B-aligned idx in y slice
#define N_Y4       ((TRAIN_LEN - Y_ALIGN) / 4)   // 49908 float4s
#define YB         10                      // 20*256*10 = 51200 >= 49908
#define OB8        (B_N / 8)               // 32768 v8-chunks in obss
#define ML_C       2.9086f
#define SL_C       1.898f
#define LOG2E      1.4426950408889634f

__device__ float    g_partS[NRED];
__device__ float    g_partS2[NRED];
__device__ float    g_obsstd;
__device__ unsigned g_count = 0;
__device__ unsigned g_flag  = 0;

// 256-bit store (sm_100a+ family): one issue slot per 32 bytes.
#define V8STORE(PTR, A0,A1,A2,A3,A4,A5,A6,A7)                               \
    asm volatile("st.global.v8.b32 [%0], {%1,%2,%3,%4,%5,%6,%7,%8};"        \
        :: "l"(PTR),                                                        \
           "r"(__float_as_uint(A0)), "r"(__float_as_uint(A1)),              \
           "r"(__float_as_uint(A2)), "r"(__float_as_uint(A3)),              \
           "r"(__float_as_uint(A4)), "r"(__float_as_uint(A5)),              \
           "r"(__float_as_uint(A6)), "r"(__float_as_uint(A7)) : "memory")

__global__ void __launch_bounds__(TPB)
k_all(const float2* __restrict__ x, const float* __restrict__ y,
      const float* __restrict__ w_yom, const float* __restrict__ w_gw,
      const float* __restrict__ w_lm,  const float* __restrict__ w_fm,
      const float* __restrict__ b0p,   const float* __restrict__ wb2p,
      float* __restrict__ out) {
    const int tid = threadIdx.x;
    const int bid = blockIdx.x;

    float* __restrict__ hnout = out + 10 * B_N;     // (B,2) interleaved
    float* __restrict__ obss  = out + 12 * B_N;

    // =====================================================================
    // REDUCER BLOCKS (bid 0..NRED-1): obsstd + release + obss (v8 stores).
    // =====================================================================
    if (bid < NRED) {
        const int r = bid;
        __shared__ int   sh_last;
        __shared__ float sh_std;

        unsigned gen = 0;
        if (tid == 0) gen = *(volatile unsigned*)&g_flag;

        // front-batched predicated loads (MLP=10, one DRAM latency)
        float4 v[YB];
        const int t0 = r * TPB + tid;               // 0..5119
#pragma unroll
        for (int k = 0; k < YB; ++k) {
            int yi = t0 + k * (NRED * TPB);
            v[k] = (yi < N_Y4)
                 ? *reinterpret_cast<const float4*>(y + Y_ALIGN + 4 * yi)
                 : make_float4(0.f, 0.f, 0.f, 0.f);
        }
        float s = 0.f, s2 = 0.f;
#pragma unroll
        for (int k = 0; k < YB; ++k) {
            s  += v[k].x + v[k].y + v[k].z + v[k].w;
            s2 += v[k].x*v[k].x + v[k].y*v[k].y
                + v[k].z*v[k].z + v[k].w*v[k].w;
        }
        if (r == 0 && tid < 3) {                    // elems 365..367
            float t = y[SPIN_LEN + tid];
            s += t; s2 += t * t;
        }
#pragma unroll
        for (int o = 16; o; o >>= 1) {
            s  += __shfl_down_sync(0xffffffffu, s, o);
            s2 += __shfl_down_sync(0xffffffffu, s2, o);
        }
        __shared__ float rs[8], rs2[8];
        int w = tid >> 5, l = tid & 31;
        if (l == 0) { rs[w] = s; rs2[w] = s2; }
        __syncthreads();
        if (tid == 0) {
            float a = 0.f, b = 0.f;
#pragma unroll
            for (int i = 0; i < TPB / 32; i++) { a += rs[i]; b += rs2[i]; }
            g_partS[r]  = a;
            g_partS2[r] = b;
            __threadfence();
            unsigned old = atomicAdd(&g_count, 1);
            sh_last = (old == NRED - 1);
        }
        __syncthreads();

        if (sh_last && tid < 32) {                  // finalize in warp 0
            double ds = 0.0, ds2 = 0.0;
            if (tid < NRED) {
                ds  = (double)__ldcg(&g_partS[tid]);
                ds2 = (double)__ldcg(&g_partS2[tid]);
            }
#pragma unroll
            for (int o = 16; o; o >>= 1) {
                ds  += __shfl_down_sync(0xffffffffu, ds, o);
                ds2 += __shfl_down_sync(0xffffffffu, ds2, o);
            }
            if (tid == 0) {
                double n = (double)N_OBS;
                g_obsstd = (float)sqrt((ds2 - ds * ds / n) / (n - 1.0));
                g_count  = 0;                       // reset for next replay
                __threadfence();
                atomicAdd(&g_flag, 1);              // release
            }
        }

        if (tid == 0) {
            while (*(volatile unsigned*)&g_flag == gen) __nanosleep(32);
            __threadfence();
            sh_std = *(volatile float*)&g_obsstd;
        }
        __syncthreads();
        const float st = sh_std;

        // obss: 32768 v8-chunks over 5120 threads = 7 predicated v8 stores
#pragma unroll
        for (int it = 0; it < 7; ++it) {
            int idx8 = it * (NRED * TPB) + r * TPB + tid;
            if (idx8 < OB8) {
                V8STORE(&obss[8 * idx8], st, st, st, st, st, st, st, st);
            }
        }
        return;
    }

    // =====================================================================
    // MAIN BLOCKS: warp-self-contained affine scan, SEG=8, v8 stores.
    // =====================================================================
    const int mb    = bid - NRED;                   // 0..NMAIN-1
    const int lane  = tid & 31;
    const int wid   = tid >> 5;                     // 0..7
    const int wbase = mb * CHUNK + wid * 256;       // warp's first element

    const unsigned gen = *(volatile unsigned*)&g_flag;   // replay-safe

    // ---- front-batched loads: 8 owned elems (4x LDG.128) + 1 halo elem
    const int og = wbase + SEG * lane;              // 32B-aligned everywhere
    float4 xa = *reinterpret_cast<const float4*>(x + og);      // elems 0,1
    float4 xb = *reinterpret_cast<const float4*>(x + og + 2);  // elems 2,3
    float4 xc = *reinterpret_cast<const float4*>(x + og + 4);  // elems 4,5
    float4 xd = *reinterpret_cast<const float4*>(x + og + 6);  // elems 6,7
    const int hg = wbase - HALO + lane;
    float2 hx = make_float2(0.f, 0.f);
    if (hg >= 0) hx = x[hg];                        // only mb0/warp0 skips

    // ---- scalar gates (uniform, fast-math) ----
    const float e1 = __expf(w_yom[0]);
    const float e2 = __expf(w_gw[0]);
    const float e3 = __expf(w_lm[0]);
    const float e4 = __expf(w_fm[0]);
    const float inv_denom = __fdividef(1.0f, e1 + e2 + e3 + e4);
    const float oo    = e1 * inv_denom;
    const float oogw  = e2 * inv_denom;
    const float ol1   = e3 * inv_denom;
    const float fbase = 1.0f - oo - oogw;
    const float ws2 = wb2p[0] * (LOG2E / SL_C);     // exp2-domain slope
    const float zc2 = (b0p[0] - ML_C * wb2p[0] / SL_C) * LOG2E;

    // ---- sigmoids (MUFU.EX2 path), 8 owned + 1 halo ----
    float uu[SEG], ff[SEG], ol[SEG];
    uu[0]=xa.x; uu[1]=xa.z; uu[2]=xb.x; uu[3]=xb.z;
    uu[4]=xc.x; uu[5]=xc.z; uu[6]=xd.x; uu[7]=xd.z;
    {
        float zz[SEG];
        zz[0]=xa.y; zz[1]=xa.w; zz[2]=xb.y; zz[3]=xb.w;
        zz[4]=xc.y; zz[5]=xc.w; zz[6]=xd.y; zz[7]=xd.w;
#pragma unroll
        for (int i = 0; i < SEG; ++i) {
            ol[i] = __fdividef(ol1, 1.0f + exp2f(-fmaf(zz[i], ws2, zc2)));
            ff[i] = fbase - ol[i];
        }
    }
    float fh = 0.f, uh = 0.f;
    if (hg >= 0) {
        float olh = __fdividef(ol1, 1.0f + exp2f(-fmaf(hx.y, ws2, zc2)));
        fh = fbase - olh;
        uh = hx.x;
    }

    // ---- halo: ordered butterfly reduction of affine (F,U); c_base = U(0)
    float c_base;
    {
        float F = fh, U = uh;
#pragma unroll
        for (int s = 1; s < 32; s <<= 1) {
            float Fo = __shfl_xor_sync(0xffffffffu, F, s);
            float Uo = __shfl_xor_sync(0xffffffffu, U, s);
            bool lower = (lane & s) == 0;
            float Fhi = lower ? Fo : F;
            float Uhi = lower ? Uo : U;
            float Flo = lower ? F  : Fo;
            float Ulo = lower ? U  : Uo;
            U = fmaf(Fhi, Ulo, Uhi);                // hi ∘ lo
            F = Fhi * Flo;
        }
        c_base = U;
    }

    // ---- owned: 3-level pair-tree compose of 8 elems, warp scan, shift ----
    float Fp, Up;
    {
        float F10 = ff[1]*ff[0], U10 = fmaf(ff[1], uu[0], uu[1]);
        float F32 = ff[3]*ff[2], U32 = fmaf(ff[3], uu[2], uu[3]);
        float F54 = ff[5]*ff[4], U54 = fmaf(ff[5], uu[4], uu[5]);
        float F76 = ff[7]*ff[6], U76 = fmaf(ff[7], uu[6], uu[7]);
        float F30 = F32*F10,     U30 = fmaf(F32, U10, U32);
        float F74 = F76*F54,     U74 = fmaf(F76, U54, U76);
        float F   = F74*F30;
        float U   = fmaf(F74, U30, U74);
#pragma unroll
        for (int d = 1; d < 32; d <<= 1) {
            float Fi = __shfl_up_sync(0xffffffffu, F, d);
            float Ui = __shfl_up_sync(0xffffffffu, U, d);
            if (lane >= d) {
                U = fmaf(F, Ui, U);
                F = F * Fi;
            }
        }
        Fp = __shfl_up_sync(0xffffffffu, F, 1);     // exclusive
        Up = __shfl_up_sync(0xffffffffu, U, 1);
        if (lane == 0) { Fp = 1.f; Up = 0.f; }
    }
    float cc[SEG];
    cc[0] = fmaf(Fp, c_base, Up);                   // state before elem 0
#pragma unroll
    for (int i = 1; i < SEG; ++i)
        cc[i] = fmaf(ff[i-1], cc[i-1], uu[i-1]);

    // ---- outputs: one v8 (256-bit) store per array per thread ----
    float* __restrict__ h_n   = out;
    float* __restrict__ c_n   = out +  1 * B_N;
    float* __restrict__ l_n   = out +  2 * B_N;
    float* __restrict__ gw_n  = out +  3 * B_N;
    float* __restrict__ bp_n  = out +  4 * B_N;
    float* __restrict__ gib   = out +  5 * B_N;
    float* __restrict__ goo   = out +  6 * B_N;
    float* __restrict__ googw = out +  7 * B_N;
    float* __restrict__ gol   = out +  8 * B_N;
    float* __restrict__ gf    = out +  9 * B_N;

    float hh[SEG];
#pragma unroll
    for (int i = 0; i < SEG; ++i) hh[i] = oo * cc[i];

    V8STORE(&h_n[og],  hh[0],hh[1],hh[2],hh[3],hh[4],hh[5],hh[6],hh[7]);
    V8STORE(&c_n[og],  cc[0],cc[1],cc[2],cc[3],cc[4],cc[5],cc[6],cc[7]);
    V8STORE(&l_n[og],  ol[0]*cc[0],ol[1]*cc[1],ol[2]*cc[2],ol[3]*cc[3],
                       ol[4]*cc[4],ol[5]*cc[5],ol[6]*cc[6],ol[7]*cc[7]);
    V8STORE(&gw_n[og], oogw*cc[0],oogw*cc[1],oogw*cc[2],oogw*cc[3],
                       oogw*cc[4],oogw*cc[5],oogw*cc[6],oogw*cc[7]);
    V8STORE(&bp_n[og], 0.f,0.f,0.f,0.f,0.f,0.f,0.f,0.f);
    V8STORE(&gib[og],  0.f,0.f,0.f,0.f,0.f,0.f,0.f,0.f);
    V8STORE(&goo[og],  oo,oo,oo,oo,oo,oo,oo,oo);
    V8STORE(&googw[og],oogw,oogw,oogw,oogw,oogw,oogw,oogw,oogw);
    V8STORE(&gol[og],  ol[0],ol[1],ol[2],ol[3],ol[4],ol[5],ol[6],ol[7]);
    V8STORE(&gf[og],   ff[0],ff[1],ff[2],ff[3],ff[4],ff[5],ff[6],ff[7]);

    // ---- per-warp poll (reducers released long ago; usually 1 load) ----
    while (*(volatile unsigned*)&g_flag == gen) __nanosleep(64);
    __threadfence();
    const float st = *(volatile float*)&g_obsstd;

    // ---- hnout interleaved {h, obsstd}: 2 v8 stores ----
    V8STORE(&hnout[2*og],
            hh[0], st, hh[1], st, hh[2], st, hh[3], st);
    V8STORE(&hnout[2*og + 8],
            hh[4], st, hh[5], st, hh[6], st, hh[7], st);
}

// ---------------------------------------------------------------------------
extern "C" void kernel_launch(void* const* d_in, const int* in_sizes, int n_in,
                              void* d_out, int out_size) {
    const float* x = (const float*)d_in[0];
    const float* y = (const float*)d_in[1];

    int base = (n_in >= 10) ? 4 : 2;
    const float* w_yom = (const float*)d_in[base + 0];
    const float* w_gw  = (const float*)d_in[base + 1];
    const float* w_lm  = (const float*)d_in[base + 2];
    const float* w_fm  = (const float*)d_in[base + 3];
    const float* b0p   = (const float*)d_in[base + 4];
    const float* wb2p  = (const float*)d_in[base + 5];

    k_all<<<NBLK, TPB>>>((const float2*)x, y,
                         w_yom, w_gw, w_lm, w_fm, b0p, wb2p,
                         (float*)d_out);
}